// round 1
// baseline (speedup 1.0000x reference)
#include <cuda_runtime.h>
#include <math.h>

// Problem constants (fixed shapes)
#define B_ROWS  4096
#define N_NODES 2048
#define N_IN    512
#define N_EVAL  1536
#define N_OUT   256
#define CHUNK   128
#define NCHUNK  12

// Persistent activation scratch: [B_ROWS, N_NODES] fp32 (32 MB)
__device__ float g_outputs[(size_t)B_ROWS * N_NODES];

// SGEMM tile config
#define BM 32
#define BN 128
#define BK 16

// ---------------------------------------------------------------------------
// Fused chunk kernel: Z[BM,128] = outputs[:, :P] @ W[i0:i0+128, :P]^T + b,
// then sequential triangular epilogue + sigmoid, writing o back to g_outputs.
// grid: 128 blocks (4096/32 rows), block: 256 threads.
// ---------------------------------------------------------------------------
__global__ __launch_bounds__(256) void chunk_kernel(const float* __restrict__ W,
                                                    const float* __restrict__ bias,
                                                    int i0)
{
    const int P = N_IN + i0;              // prefix length (multiple of 16)

    __shared__ float As[2][BK * 34];      // [k][m], padded
    __shared__ float Bs[2][BK * 132];     // [k][c], padded (132 % 4 == 0 for float4)
    __shared__ float Zs[CHUNK * 33];      // [c][m], padded

    const int tid  = threadIdx.x;
    const int brow = blockIdx.x * BM;

    // compute-thread mapping: 16x16 thread grid, each does 2 rows x 8 cols
    const int tx = tid & 15;
    const int ty = tid >> 4;
    const int r0 = 2 * ty;                // local row 0..30
    const int c0 = 8 * tx;                // local col 0..120

    // global-load mappings
    const int am = tid >> 3;              // A: row 0..31
    const int ak = (tid & 7) * 2;         // A: k offset (even)
    const int bc = tid >> 1;              // B: chunk-col 0..127
    const int bk = (tid & 1) * 8;         // B: k offset 0 or 8

    const float* Ag = g_outputs + (size_t)(brow + am) * N_NODES;
    const float* Bg = W + (size_t)(i0 + bc) * N_NODES;

    float acc[2][8];
#pragma unroll
    for (int i = 0; i < 2; i++)
#pragma unroll
        for (int j = 0; j < 8; j++) acc[i][j] = 0.f;

    const int nIter = P / BK;

    // preload tile 0
    {
        float2 av = *(const float2*)(Ag + ak);
        As[0][(ak    ) * 34 + am] = av.x;
        As[0][(ak + 1) * 34 + am] = av.y;
        float4 b0 = *(const float4*)(Bg + bk);
        float4 b1 = *(const float4*)(Bg + bk + 4);
        Bs[0][(bk + 0) * 132 + bc] = b0.x;
        Bs[0][(bk + 1) * 132 + bc] = b0.y;
        Bs[0][(bk + 2) * 132 + bc] = b0.z;
        Bs[0][(bk + 3) * 132 + bc] = b0.w;
        Bs[0][(bk + 4) * 132 + bc] = b1.x;
        Bs[0][(bk + 5) * 132 + bc] = b1.y;
        Bs[0][(bk + 6) * 132 + bc] = b1.z;
        Bs[0][(bk + 7) * 132 + bc] = b1.w;
    }
    __syncthreads();

    int buf = 0;
    for (int t = 0; t < nIter; t++) {
        float2 av;
        float4 b0v, b1v;
        const bool more = (t + 1 < nIter);
        if (more) {
            const float* Ag2 = Ag + (t + 1) * BK;
            const float* Bg2 = Bg + (t + 1) * BK;
            av  = *(const float2*)(Ag2 + ak);
            b0v = *(const float4*)(Bg2 + bk);
            b1v = *(const float4*)(Bg2 + bk + 4);
        }

        // compute on current buffer
#pragma unroll
        for (int kk = 0; kk < BK; kk++) {
            float2 a  = *(const float2*)&As[buf][kk * 34 + r0];
            float4 bb0 = *(const float4*)&Bs[buf][kk * 132 + c0];
            float4 bb1 = *(const float4*)&Bs[buf][kk * 132 + c0 + 4];
            float bv[8] = {bb0.x, bb0.y, bb0.z, bb0.w, bb1.x, bb1.y, bb1.z, bb1.w};
#pragma unroll
            for (int j = 0; j < 8; j++) {
                acc[0][j] += a.x * bv[j];
                acc[1][j] += a.y * bv[j];
            }
        }

        if (more) {
            const int nb = buf ^ 1;
            As[nb][(ak    ) * 34 + am] = av.x;
            As[nb][(ak + 1) * 34 + am] = av.y;
            Bs[nb][(bk + 0) * 132 + bc] = b0v.x;
            Bs[nb][(bk + 1) * 132 + bc] = b0v.y;
            Bs[nb][(bk + 2) * 132 + bc] = b0v.z;
            Bs[nb][(bk + 3) * 132 + bc] = b0v.w;
            Bs[nb][(bk + 4) * 132 + bc] = b1v.x;
            Bs[nb][(bk + 5) * 132 + bc] = b1v.y;
            Bs[nb][(bk + 6) * 132 + bc] = b1v.z;
            Bs[nb][(bk + 7) * 132 + bc] = b1v.w;
        }
        __syncthreads();
        buf ^= 1;
    }

    // stage Z (+bias) into smem as [c][m]
    const float* bptr = bias + i0;
#pragma unroll
    for (int j = 0; j < 8; j++) {
        float bv = bptr[c0 + j];
        Zs[(c0 + j) * 33 + r0    ] = acc[0][j] + bv;
        Zs[(c0 + j) * 33 + r0 + 1] = acc[1][j] + bv;
    }
    __syncthreads();

    // -----------------------------------------------------------------------
    // Triangular epilogue. Each warp owns 4 batch rows; within a row, 8 lanes
    // (sub = lane&7) split the intra-chunk dot product, butterfly-reduce.
    // Rows are independent -> only __syncwarp per node.
    // -----------------------------------------------------------------------
    {
        const int warp = tid >> 5;
        const int lane = tid & 31;
        const int mloc = lane >> 3;       // 0..3
        const int sub  = lane & 7;        // 0..7
        const int m    = warp * 4 + mloc; // 0..31

        for (int c = 0; c < CHUNK; c++) {
            const float* wrow = W + (size_t)(i0 + c) * N_NODES + P;
            float s = 0.f;
            for (int d = sub; d < c; d += 8)
                s += wrow[d] * Zs[d * 33 + m];
            s += __shfl_xor_sync(0xffffffffu, s, 1);
            s += __shfl_xor_sync(0xffffffffu, s, 2);
            s += __shfl_xor_sync(0xffffffffu, s, 4);
            float z  = Zs[c * 33 + m] + s;
            float t5 = fminf(fmaxf(5.0f * z, -60.0f), 60.0f);
            float o  = 1.0f / (1.0f + expf(-t5));
            if (sub == 0) Zs[c * 33 + m] = o;
            __syncwarp();
        }
    }
    __syncthreads();

    // write back: g_outputs[brow+m][P + c]
    {
        const int m2  = tid >> 3;          // 0..31
        const int cc0 = (tid & 7) * 16;    // 0..112
        float* dst = g_outputs + (size_t)(brow + m2) * N_NODES + P + cc0;
#pragma unroll
        for (int j = 0; j < 16; j++)
            dst[j] = Zs[(cc0 + j) * 33 + m2];
    }
}

// ---------------------------------------------------------------------------
__global__ void init_kernel(const float* __restrict__ x)
{
    int idx = blockIdx.x * blockDim.x + threadIdx.x;
    if (idx < B_ROWS * N_IN) {
        int r = idx >> 9;          // /512
        int c = idx & 511;
        g_outputs[(size_t)r * N_NODES + c] = x[idx];
    }
}

__global__ void copy_kernel(float* __restrict__ out)
{
    int idx = blockIdx.x * blockDim.x + threadIdx.x;
    if (idx < B_ROWS * N_OUT) {
        int r = idx >> 8;          // /256
        int c = idx & 255;
        out[idx] = g_outputs[(size_t)r * N_NODES + (N_NODES - N_OUT) + c];
    }
}

// ---------------------------------------------------------------------------
extern "C" void kernel_launch(void* const* d_in, const int* in_sizes, int n_in,
                              void* d_out, int out_size)
{
    (void)in_sizes; (void)n_in; (void)out_size;
    const float* x  = (const float*)d_in[0];
    const float* W  = (const float*)d_in[1];
    const float* b  = (const float*)d_in[2];
    float* out = (float*)d_out;

    init_kernel<<<(B_ROWS * N_IN + 255) / 256, 256>>>(x);
    for (int k = 0; k < NCHUNK; k++)
        chunk_kernel<<<B_ROWS / BM, 256>>>(W, b, k * CHUNK);
    copy_kernel<<<(B_ROWS * N_OUT + 255) / 256, 256>>>(out);
}